// round 12
// baseline (speedup 1.0000x reference)
#include <cuda_runtime.h>
#include <cuda_fp16.h>

#define NN 50000
#define NE 1600000
#define TOT (NE + NN)
#define DIN 128
#define DH  64
#define NCHUNK 196           // ceil(NN/256)
#define BN_EPS 1e-5f
#define FXS 16777216.0f      // 2^24 fixed point for degree sum
#define MASK40 ((1ull << 40) - 1)

// ---------------- persistent scratch ----------------
__device__ int                g_src[NE];
__device__ unsigned int       g_dr[NE];        // (dst<<16)|rank
__device__ float              g_w[NE];
__device__ unsigned long long g_dc[NN];        // zero at entry (re-zeroed after read each run)
__device__ float              g_dinv[NN];
__device__ int                g_rowstart[NN];  // exclusive prefix within 256-chunk
__device__ int                g_bsum[NCHUNK];  // chunk offsets
__device__ int                g_scanctr;       // last-block counter (reset by last block)
__device__ __align__(16) int2    g_cv[TOT];
__device__ __align__(16) __half2 g_h[NN * (DH / 2)];
__device__ __align__(16) float   g_agg[NN * DH];
__device__ float g_sum1[DH], g_sq1[DH], g_sum2[DH], g_sq2[DH];   // zeroed in k_pre
__device__ unsigned          g_count;          // barrier arrivals (returns to 0)
__device__ volatile unsigned g_gen;            // barrier generation (monotonic)

// ---------------- f32x2 packed FMA (sm_10x FFMA2, PTX-only) ----------------
__device__ __forceinline__ unsigned long long bcast2(float x) {
    unsigned long long r; asm("mov.b64 %0, {%1,%1};" : "=l"(r) : "f"(x)); return r;
}
__device__ __forceinline__ void fma2(unsigned long long& d, unsigned long long a, unsigned long long b) {
    asm("fma.rn.f32x2 %0, %1, %2, %0;" : "+l"(d) : "l"(a), "l"(b));
}
__device__ __forceinline__ float2 unpack2(unsigned long long v) {
    float2 f; asm("mov.b64 {%0,%1}, %2;" : "=f"(f.x), "=f"(f.y) : "l"(v)); return f;
}

__device__ __forceinline__ int rowbeg(int i) { return g_rowstart[i] + g_bsum[i >> 8]; }

// ---------------- grid barrier for k_pre (one-wave grid; gemm1 never waits on us) ----
__device__ __forceinline__ void gbar() {
    __threadfence();
    __syncthreads();
    if (threadIdx.x == 0) {
        unsigned gen = g_gen;
        if (atomicAdd(&g_count, 1) == gridDim.x - 1) {
            g_count = 0;
            __threadfence();
            g_gen = gen + 1;
        } else {
            while (g_gen == gen) __nanosleep(64);
            __threadfence();
        }
    }
    __syncthreads();
}

// ---------------- k_pre: edge_prep -> scan -> fill, one persistent launch ----------------
__global__ void __launch_bounds__(256) k_pre(const void* __restrict__ ei,
                                             const float* __restrict__ wsc,
                                             const float* __restrict__ wfc,
                                             const float* __restrict__ alpha) {
    __shared__ int si[256];
    __shared__ int s_last;
    const int tid = threadIdx.x, bid = blockIdx.x, nb = gridDim.x;

    // ---- edge prep (one packed u64 atomic per edge) ----
    {
        // dtype probe: 8 spread samples; identical deterministic result per block
        const int* p32 = (const int*)ei;
        int is64 = 1;
        #pragma unroll
        for (int j = 0; j < 8; ++j) {
            int k = j * (NE / 8) + j + 1;
            if (__ldg(&p32[2 * k + 1]) != 0) is64 = 0;   // int64 LE high word == 0
        }
        float a = 1.f / (1.f + __expf(-__ldg(alpha)));
        for (int e = bid * 256 + tid; e < NE; e += nb * 256) {
            int s, d;
            if (is64) {
                const long long* p = (const long long*)ei;
                s = (int)__ldg(&p[e]);
                d = (int)__ldg(&p[NE + e]);
            } else {
                const int* p = (const int*)ei;
                s = __ldg(&p[e]);
                d = __ldg(&p[NE + e]);
            }
            s = min(max(s, 0), NN - 1);
            d = min(max(d, 0), NN - 1);
            float w = a * __ldg(&wsc[e]) + (1.f - a) * __ldg(&wfc[e]);
            unsigned long long wfx = (unsigned long long)(w * FXS + 0.5f);
            unsigned long long old = atomicAdd(&g_dc[d], (1ull << 40) | wfx);
            unsigned int rank = (unsigned int)(old >> 40) + 1u;   // rank 0 = self loop
            rank = min(rank, 65535u);
            g_src[e] = s;
            g_w[e]   = w;
            g_dr[e]  = ((unsigned int)d << 16) | rank;
        }
    }
    gbar();

    // ---- scan pass 1 (256-chunks) + dinv + zero g_dc/stats; last block does pass 2 ----
    {
        for (int c = bid; c < NCHUNK; c += nb) {
            int i = c * 256 + tid;
            int v = 0; float deg = 1.0f;
            if (i < NN) {
                unsigned long long dc = g_dc[i];
                g_dc[i] = 0ull;                           // ready for next replay
                v = (int)(dc >> 40) + 1;                  // + self loop
                deg = 1.0f + (float)(dc & MASK40) * (1.0f / FXS);
            }
            si[tid] = v; __syncthreads();
            for (int off = 1; off < 256; off <<= 1) {
                int u = (tid >= off) ? si[tid - off] : 0;
                __syncthreads();
                si[tid] += u; __syncthreads();
            }
            if (i < NN) {
                g_rowstart[i] = si[tid] - v;              // exclusive within chunk
                g_dinv[i] = rsqrtf(deg);
            }
            if (tid == 255) g_bsum[c] = si[tid];
            __syncthreads();
        }
        if (bid == 0 && tid < DH) {
            g_sum1[tid] = 0.f; g_sq1[tid] = 0.f; g_sum2[tid] = 0.f; g_sq2[tid] = 0.f;
        }
        __threadfence();
        __syncthreads();
        if (tid == 0) s_last = (atomicAdd(&g_scanctr, 1) == nb - 1);
        __syncthreads();
        if (s_last) {
            if (tid == 0) g_scanctr = 0;                  // reset for next replay
            int v = (tid < NCHUNK) ? g_bsum[tid] : 0;
            si[tid] = v; __syncthreads();
            for (int off = 1; off < 256; off <<= 1) {
                int u = (tid >= off) ? si[tid - off] : 0;
                __syncthreads();
                si[tid] += u; __syncthreads();
            }
            if (tid < NCHUNK) g_bsum[tid] = si[tid] - v;  // exclusive chunk offsets
        }
    }
    gbar();

    // ---- CSR fill (atomic-free) ----
    for (int e = bid * 256 + tid; e < TOT; e += nb * 256) {
        if (e < NE) {
            unsigned int dr = g_dr[e];
            int d = (int)(dr >> 16);
            int rank = (int)(dr & 0xffffu);
            int s = g_src[e];
            int p = min(rowbeg(d) + rank, TOT - 1);
            g_cv[p] = make_int2(s, __float_as_int(g_dinv[s] * g_w[e]));
        } else {
            int i = e - NE;
            g_cv[rowbeg(i)] = make_int2(i, __float_as_int(g_dinv[i]));
        }
    }
}

// ---------------- GEMM1: g_h(fp16) = x[N,128] @ W1[128,64] (side stream) ----------------
__global__ void __launch_bounds__(256) k_gemm1(const float* __restrict__ x,
                                               const float* __restrict__ W1) {
    __shared__ __align__(16) float sW[DIN * DH];      // 32 KB
    for (int i = threadIdx.x; i < DIN * DH; i += 256) sW[i] = W1[i];
    __syncthreads();
    int warp = threadIdx.x >> 5, lane = threadIdx.x & 31;
    int nbase = blockIdx.x * 32 + warp * 4;
    if (nbase >= NN) return;
    int n0 = nbase, n1 = min(nbase + 1, NN - 1), n2 = min(nbase + 2, NN - 1), n3 = min(nbase + 3, NN - 1);
    const float4* x0 = (const float4*)(x + (size_t)n0 * DIN);
    const float4* x1 = (const float4*)(x + (size_t)n1 * DIN);
    const float4* x2 = (const float4*)(x + (size_t)n2 * DIN);
    const float4* x3 = (const float4*)(x + (size_t)n3 * DIN);
    unsigned long long a0 = 0ULL, a1 = 0ULL, a2 = 0ULL, a3 = 0ULL;
    #pragma unroll
    for (int kk = 0; kk < DIN / 4; ++kk) {
        float ra[4], rb[4], rc[4], rd[4];
        *(float4*)ra = __ldg(x0 + kk);
        *(float4*)rb = __ldg(x1 + kk);
        *(float4*)rc = __ldg(x2 + kk);
        *(float4*)rd = __ldg(x3 + kk);
        #pragma unroll
        for (int u = 0; u < 4; ++u) {
            unsigned long long w = *(const unsigned long long*)&sW[(4 * kk + u) * DH + 2 * lane];
            fma2(a0, bcast2(ra[u]), w);
            fma2(a1, bcast2(rb[u]), w);
            fma2(a2, bcast2(rc[u]), w);
            fma2(a3, bcast2(rd[u]), w);
        }
    }
    g_h[(size_t)n0 * 32 + lane] = __float22half2_rn(unpack2(a0));
    if (nbase + 1 < NN) g_h[(size_t)n1 * 32 + lane] = __float22half2_rn(unpack2(a1));
    if (nbase + 2 < NN) g_h[(size_t)n2 * 32 + lane] = __float22half2_rn(unpack2(a2));
    if (nbase + 3 < NN) g_h[(size_t)n3 * 32 + lane] = __float22half2_rn(unpack2(a3));
}

// ---------------- CSR gather agg (row scaled by dinv[dst]) + bias, fused column stats ----
__global__ void __launch_bounds__(256) k_agg(const float* __restrict__ bias,
                                             float* __restrict__ gsum,
                                             float* __restrict__ gsq) {
    __shared__ float s_sum[DH], s_sq[DH];
    if (threadIdx.x < DH) { s_sum[threadIdx.x] = 0.f; s_sq[threadIdx.x] = 0.f; }
    __syncthreads();
    int gw = blockIdx.x * 8 + (threadIdx.x >> 5);
    int lane = threadIdx.x & 31;
    int beg = rowbeg(gw);
    int end = (gw == NN - 1) ? TOT : rowbeg(gw + 1);
    const __half2* hp = g_h;
    float2 acc = {0.f, 0.f};
    int j = beg;
    for (; j + 4 <= end; j += 4) {
        int2 c0 = g_cv[j], c1 = g_cv[j + 1], c2 = g_cv[j + 2], c3 = g_cv[j + 3];
        float2 h0 = __half22float2(__ldg(&hp[(size_t)c0.x * 32 + lane]));
        float2 h1 = __half22float2(__ldg(&hp[(size_t)c1.x * 32 + lane]));
        float2 h2 = __half22float2(__ldg(&hp[(size_t)c2.x * 32 + lane]));
        float2 h3 = __half22float2(__ldg(&hp[(size_t)c3.x * 32 + lane]));
        float v0 = __int_as_float(c0.y), v1 = __int_as_float(c1.y);
        float v2 = __int_as_float(c2.y), v3 = __int_as_float(c3.y);
        acc.x += v0 * h0.x; acc.y += v0 * h0.y;
        acc.x += v1 * h1.x; acc.y += v1 * h1.y;
        acc.x += v2 * h2.x; acc.y += v2 * h2.y;
        acc.x += v3 * h3.x; acc.y += v3 * h3.y;
    }
    for (; j < end; ++j) {
        int2 c = g_cv[j];
        float2 hv = __half22float2(__ldg(&hp[(size_t)c.x * 32 + lane]));
        float v = __int_as_float(c.y);
        acc.x += v * hv.x; acc.y += v * hv.y;
    }
    float di = g_dinv[gw];
    acc.x = acc.x * di + __ldg(&bias[2 * lane]);
    acc.y = acc.y * di + __ldg(&bias[2 * lane + 1]);
    *(float2*)&g_agg[(size_t)gw * DH + 2 * lane] = acc;
    atomicAdd(&s_sum[2 * lane],     acc.x);
    atomicAdd(&s_sum[2 * lane + 1], acc.y);
    atomicAdd(&s_sq[2 * lane],      acc.x * acc.x);
    atomicAdd(&s_sq[2 * lane + 1],  acc.y * acc.y);
    __syncthreads();
    if (threadIdx.x < DH) {
        atomicAdd(&gsum[threadIdx.x], s_sum[threadIdx.x]);
        atomicAdd(&gsq[threadIdx.x],  s_sq[threadIdx.x]);
    }
}

// ---------------- GEMM2: g_h(fp16) = relu(bn1(g_agg)) @ W2[64,64] ----------------
__global__ void __launch_bounds__(256) k_gemm2(const float* __restrict__ W2,
                                               const float* __restrict__ gamma,
                                               const float* __restrict__ beta) {
    __shared__ __align__(16) float sW[DH * DH];
    __shared__ __align__(16) float ssc[DH], ssh[DH];
    for (int i = threadIdx.x; i < DH * DH; i += 256) sW[i] = W2[i];
    if (threadIdx.x < DH) {
        int c = threadIdx.x;
        float mean = g_sum1[c] * (1.f / NN);
        float var  = g_sq1[c] * (1.f / NN) - mean * mean;
        float inv  = rsqrtf(var + BN_EPS);
        float sc   = __ldg(&gamma[c]) * inv;
        ssc[c] = sc;
        ssh[c] = __ldg(&beta[c]) - mean * sc;
    }
    __syncthreads();
    int warp = threadIdx.x >> 5, lane = threadIdx.x & 31;
    int nbase = blockIdx.x * 32 + warp * 4;
    if (nbase >= NN) return;
    int n0 = nbase, n1 = min(nbase + 1, NN - 1), n2 = min(nbase + 2, NN - 1), n3 = min(nbase + 3, NN - 1);
    const float4* x0 = (const float4*)(g_agg + (size_t)n0 * DH);
    const float4* x1 = (const float4*)(g_agg + (size_t)n1 * DH);
    const float4* x2 = (const float4*)(g_agg + (size_t)n2 * DH);
    const float4* x3 = (const float4*)(g_agg + (size_t)n3 * DH);
    unsigned long long a0 = 0ULL, a1 = 0ULL, a2 = 0ULL, a3 = 0ULL;
    #pragma unroll
    for (int kk = 0; kk < DH / 4; ++kk) {
        float ra[4], rb[4], rc[4], rd[4];
        *(float4*)ra = __ldg(x0 + kk);
        *(float4*)rb = __ldg(x1 + kk);
        *(float4*)rc = __ldg(x2 + kk);
        *(float4*)rd = __ldg(x3 + kk);
        float scs[4], shs[4];
        *(float4*)scs = *(float4*)&ssc[4 * kk];
        *(float4*)shs = *(float4*)&ssh[4 * kk];
        #pragma unroll
        for (int u = 0; u < 4; ++u) {
            unsigned long long w = *(const unsigned long long*)&sW[(4 * kk + u) * DH + 2 * lane];
            float va = fmaxf(fmaf(ra[u], scs[u], shs[u]), 0.f);
            float vb = fmaxf(fmaf(rb[u], scs[u], shs[u]), 0.f);
            float vc = fmaxf(fmaf(rc[u], scs[u], shs[u]), 0.f);
            float vd = fmaxf(fmaf(rd[u], scs[u], shs[u]), 0.f);
            fma2(a0, bcast2(va), w);
            fma2(a1, bcast2(vb), w);
            fma2(a2, bcast2(vc), w);
            fma2(a3, bcast2(vd), w);
        }
    }
    g_h[(size_t)n0 * 32 + lane] = __float22half2_rn(unpack2(a0));
    if (nbase + 1 < NN) g_h[(size_t)n1 * 32 + lane] = __float22half2_rn(unpack2(a1));
    if (nbase + 2 < NN) g_h[(size_t)n2 * 32 + lane] = __float22half2_rn(unpack2(a2));
    if (nbase + 3 < NN) g_h[(size_t)n3 * 32 + lane] = __float22half2_rn(unpack2(a3));
}

// ---------------- final: out = relu(bn2(g_agg)) ----------------
__global__ void __launch_bounds__(256) k_final(const float* __restrict__ gamma,
                                               const float* __restrict__ beta,
                                               float* __restrict__ out) {
    __shared__ float ssc[DH], ssh[DH];
    if (threadIdx.x < DH) {
        int c = threadIdx.x;
        float mean = g_sum2[c] * (1.f / NN);
        float var  = g_sq2[c] * (1.f / NN) - mean * mean;
        float inv  = rsqrtf(var + BN_EPS);
        float sc   = __ldg(&gamma[c]) * inv;
        ssc[c] = sc;
        ssh[c] = __ldg(&beta[c]) - mean * sc;
    }
    __syncthreads();
    int idx = blockIdx.x * blockDim.x + threadIdx.x;   // over NN*16 float4s
    if (idx >= NN * (DH / 4)) return;
    float4 v = ((const float4*)g_agg)[idx];
    int cb = (idx & (DH / 4 - 1)) * 4;
    v.x = fmaxf(fmaf(v.x, ssc[cb + 0], ssh[cb + 0]), 0.f);
    v.y = fmaxf(fmaf(v.y, ssc[cb + 1], ssh[cb + 1]), 0.f);
    v.z = fmaxf(fmaf(v.z, ssc[cb + 2], ssh[cb + 2]), 0.f);
    v.w = fmaxf(fmaf(v.w, ssc[cb + 3], ssh[cb + 3]), 0.f);
    ((float4*)out)[idx] = v;
}

// ---------------- launch: 6 kernels ----------------
extern "C" void kernel_launch(void* const* d_in, const int* in_sizes, int n_in,
                              void* d_out, int out_size) {
    const float* x      = (const float*)d_in[0];
    const void*  ei_sc  = d_in[1];
    const float* wsc    = (const float*)d_in[2];
    // d_in[3] = edge_index_fc (unused by the reference math)
    const float* wfc    = (const float*)d_in[4];
    const float* alpha  = (const float*)d_in[5];
    const float* W1     = (const float*)d_in[6];
    const float* b1     = (const float*)d_in[7];
    const float* W2     = (const float*)d_in[8];
    const float* b2     = (const float*)d_in[9];
    const float* gamma1 = (const float*)d_in[10];
    const float* beta1  = (const float*)d_in[11];
    const float* gamma2 = (const float*)d_in[12];
    const float* beta2  = (const float*)d_in[13];
    float*       out    = (float*)d_out;

    const int TB = 256;
    float* d_sum1; cudaGetSymbolAddress((void**)&d_sum1, g_sum1);
    float* d_sq1;  cudaGetSymbolAddress((void**)&d_sq1,  g_sq1);
    float* d_sum2; cudaGetSymbolAddress((void**)&d_sum2, g_sum2);
    float* d_sq2;  cudaGetSymbolAddress((void**)&d_sq2,  g_sq2);

    static int npre = 0;
    static cudaStream_t s2 = nullptr;
    static cudaEvent_t ev_fork = nullptr, ev_join = nullptr;
    if (!npre) {
        int sm = 148, maxb = 0;
        cudaDeviceGetAttribute(&sm, cudaDevAttrMultiProcessorCount, 0);
        cudaOccupancyMaxActiveBlocksPerMultiprocessor(&maxb, k_pre, TB, 0);
        if (maxb < 1) maxb = 1;
        npre = sm * maxb;   // one wave -> k_pre's grid barrier is deadlock-free
        cudaStreamCreateWithFlags(&s2, cudaStreamNonBlocking);
        cudaEventCreateWithFlags(&ev_fork, cudaEventDisableTiming);
        cudaEventCreateWithFlags(&ev_join, cudaEventDisableTiming);
    }

    // fork: gemm1 (x,W1 only) on side stream; k_pre never waits on it -> no deadlock,
    // and gemm1 makes independent forward progress so k_pre's wave becomes resident.
    cudaEventRecord(ev_fork, 0);
    cudaStreamWaitEvent(s2, ev_fork, 0);
    k_gemm1<<<(NN + 31) / 32, TB, 0, s2>>>(x, W1);
    cudaEventRecord(ev_join, s2);

    k_pre<<<npre, TB>>>(ei_sc, wsc, wfc, alpha);

    cudaStreamWaitEvent(0, ev_join, 0);   // join before consuming g_h
    k_agg<<<NN / 8, TB>>>(b1, d_sum1, d_sq1);
    k_gemm2<<<(NN + 31) / 32, TB>>>(W2, gamma1, beta1);
    k_agg<<<NN / 8, TB>>>(b2, d_sum2, d_sq2);
    k_final<<<(NN * (DH / 4) + TB - 1) / TB, TB>>>(gamma2, beta2, out);
}

// round 15
// speedup vs baseline: 2.0238x; 2.0238x over previous
#include <cuda_runtime.h>
#include <cuda_fp16.h>

#define NN 50000
#define NE 1600000
#define TOT (NE + NN)
#define DIN 128
#define DH  64
#define SCAN_B 512
#define NB_SCAN 98   // ceil(NN/512)
#define BN_EPS 1e-5f
#define FXS 16777216.0f
#define MASK40 ((1ull << 40) - 1)
#define GBLK 391     // ceil(NN/128): 128 rows per block (8 warps x 16 rows)

// ---------------- scratch ----------------
__device__ int                g_src[NE];
__device__ unsigned int       g_dr[NE];
__device__ float              g_w[NE];
__device__ unsigned long long g_dc[NN];
__device__ float              g_dinv[NN];
__device__ int                g_rowstart[NN];
__device__ int                g_bsum[NB_SCAN];
__device__ int                g_scanctr;
__device__ __align__(16) int2    g_cv[TOT];
__device__ __align__(16) __half2 g_h[NN * (DH / 2)];
__device__ __align__(16) float   g_agg[NN * DH];
__device__ float g_sum1[DH], g_sq1[DH], g_sum2[DH], g_sq2[DH];
__device__ int   g_is64 = 1;

__device__ __forceinline__ unsigned h2u(float a, float b) {
    __half2 h = __floats2half2_rn(a, b);
    return *reinterpret_cast<unsigned*>(&h);
}
#define MMA16816(c, a0, a1, a2, a3, b0, b1) \
    asm volatile("mma.sync.aligned.m16n8k16.row.col.f32.f16.f16.f32 " \
        "{%0,%1,%2,%3},{%4,%5,%6,%7},{%8,%9},{%0,%1,%2,%3};" \
        : "+f"((c)[0]), "+f"((c)[1]), "+f"((c)[2]), "+f"((c)[3]) \
        : "r"(a0), "r"(a1), "r"(a2), "r"(a3), "r"(b0), "r"(b1))

// ---------------- init + dtype probe ----------------
__global__ void k_init(const int* __restrict__ ei32) {
    int i = blockIdx.x * blockDim.x + threadIdx.x;
    if (i < DH) { g_sum1[i] = 0.f; g_sq1[i] = 0.f; g_sum2[i] = 0.f; g_sq2[i] = 0.f; }
    if (blockIdx.x == 0 && threadIdx.x < 256) {
        int k = threadIdx.x * (NE / 256);
        if (ei32[2 * k + 1] != 0) g_is64 = 0;
    }
}

// ---------------- edge prep (one packed u64 atomic per edge) ----------------
__global__ void k_edge_prep(const void* __restrict__ ei,
                            const float* __restrict__ wsc,
                            const float* __restrict__ wfc,
                            const float* __restrict__ alpha) {
    int e = blockIdx.x * blockDim.x + threadIdx.x;
    if (e >= NE) return;
    float a = 1.f / (1.f + __expf(-__ldg(alpha)));
    int s, d;
    if (g_is64) {
        const long long* p = (const long long*)ei;
        s = (int)__ldg(&p[e]);
        d = (int)__ldg(&p[NE + e]);
    } else {
        const int* p = (const int*)ei;
        s = __ldg(&p[e]);
        d = __ldg(&p[NE + e]);
    }
    s = min(max(s, 0), NN - 1);
    d = min(max(d, 0), NN - 1);
    float w = a * __ldg(&wsc[e]) + (1.f - a) * __ldg(&wfc[e]);
    unsigned long long wfx = (unsigned long long)(w * FXS + 0.5f);
    unsigned long long old = atomicAdd(&g_dc[d], (1ull << 40) | wfx);
    unsigned int rank = (unsigned int)(old >> 40) + 1u;   // rank 0 = self loop
    rank = min(rank, 65535u);
    g_src[e] = s;
    g_w[e]   = w;
    g_dr[e]  = ((unsigned int)d << 16) | rank;
}

// ---------------- fused scan + dinv (last block scans block sums) ----------------
__global__ void __launch_bounds__(SCAN_B) k_scan() {
    __shared__ int s[SCAN_B];
    __shared__ int is_last;
    int t = threadIdx.x;
    int i = blockIdx.x * SCAN_B + t;
    int v = 0;
    float deg = 1.0f;
    if (i < NN) {
        unsigned long long dc = g_dc[i];
        g_dc[i] = 0ull;
        v = (int)(dc >> 40) + 1;
        deg = 1.0f + (float)(dc & MASK40) * (1.0f / FXS);
    }
    s[t] = v; __syncthreads();
    for (int off = 1; off < SCAN_B; off <<= 1) {
        int u = (t >= off) ? s[t - off] : 0;
        __syncthreads();
        s[t] += u; __syncthreads();
    }
    if (i < NN) {
        g_rowstart[i] = s[t] - v;
        g_dinv[i] = rsqrtf(deg);
    }
    if (t == SCAN_B - 1) g_bsum[blockIdx.x] = s[t];
    __threadfence();
    if (t == 0) is_last = (atomicAdd(&g_scanctr, 1) == NB_SCAN - 1);
    __syncthreads();
    if (is_last) {
        if (t == 0) g_scanctr = 0;
        if (t < 128) {
            __shared__ int bs[128];
            int bv = (t < NB_SCAN) ? g_bsum[t] : 0;
            bs[t] = bv;
            __syncthreads();
            for (int off = 1; off < 128; off <<= 1) {
                int u = (t >= off) ? bs[t - off] : 0;
                __syncthreads();
                bs[t] += u; __syncthreads();
            }
            if (t < NB_SCAN) g_bsum[t] = bs[t] - bv;
        }
    }
}

__device__ __forceinline__ int rowbeg(int i) { return g_rowstart[i] + g_bsum[i >> 9]; }

// ---------------- CSR fill (atomic-free) ----------------
__global__ void k_fill() {
    int e = blockIdx.x * blockDim.x + threadIdx.x;
    if (e < NE) {
        unsigned int dr = g_dr[e];
        int d = (int)(dr >> 16);
        int rank = (int)(dr & 0xffffu);
        int s = g_src[e];
        int p = min(rowbeg(d) + rank, TOT - 1);
        g_cv[p] = make_int2(s, __float_as_int(g_dinv[s] * g_w[e]));
    } else if (e < NE + NN) {
        int i = e - NE;
        g_cv[rowbeg(i)] = make_int2(i, __float_as_int(g_dinv[i]));
    }
}

// ---------------- GEMM1 (mma.sync m16n8k16): g_h = fp16(x[N,128] @ W1[128,64]) ----------
#define P1 136   // smem pitch (halves) for W1^T rows: quad stride 4 banks, conflict-free
__global__ void __launch_bounds__(256) k_gemm1_mma(const float* __restrict__ x,
                                                   const float* __restrict__ W1) {
    __shared__ __align__(16) __half sWT[64 * P1];   // W1^T: [n][k] fp16
    const int tid = threadIdx.x, warp = tid >> 5, lane = tid & 31;
    const int quad = lane >> 2, tq = lane & 3;

    for (int i = tid; i < 64 * DIN; i += 256) {
        int n = i & 63, k = i >> 6;
        sWT[n * P1 + k] = __float2half(__ldg(&W1[k * 64 + n]));
    }
    __syncthreads();

    int r0 = blockIdx.x * 128 + warp * 16;
    int ra  = min(r0 + quad,     NN - 1);
    int ra8 = min(r0 + quad + 8, NN - 1);
    const float* xr  = x + (size_t)ra  * DIN;
    const float* xr8 = x + (size_t)ra8 * DIN;

    float acc[8][4];
    #pragma unroll
    for (int n = 0; n < 8; ++n) { acc[n][0] = acc[n][1] = acc[n][2] = acc[n][3] = 0.f; }

    #pragma unroll
    for (int ks = 0; ks < 8; ++ks) {
        int k0 = ks * 16 + tq * 2;
        float2 v0 = __ldg((const float2*)&xr[k0]);
        float2 v1 = __ldg((const float2*)&xr8[k0]);
        float2 v2 = __ldg((const float2*)&xr[k0 + 8]);
        float2 v3 = __ldg((const float2*)&xr8[k0 + 8]);
        unsigned a0 = h2u(v0.x, v0.y), a1 = h2u(v1.x, v1.y);
        unsigned a2 = h2u(v2.x, v2.y), a3 = h2u(v3.x, v3.y);
        #pragma unroll
        for (int n = 0; n < 8; ++n) {
            const __half* bp = &sWT[(n * 8 + quad) * P1 + k0];
            unsigned b0 = *(const unsigned*)bp;
            unsigned b1 = *(const unsigned*)(bp + 8);
            MMA16816(acc[n], a0, a1, a2, a3, b0, b1);
        }
    }

    unsigned* gh = (unsigned*)g_h;
    int r = r0 + quad;
    #pragma unroll
    for (int n = 0; n < 8; ++n) {
        int cw = n * 4 + tq;   // half2 index of col = n*8 + tq*2
        if (r < NN)     gh[(size_t)r * 32 + cw]       = h2u(acc[n][0], acc[n][1]);
        if (r + 8 < NN) gh[(size_t)(r + 8) * 32 + cw] = h2u(acc[n][2], acc[n][3]);
    }
}

// ---------------- GEMM2 (mma.sync): g_h = fp16(relu(bn1(g_agg)) @ W2[64,64]) -----------
#define P2 72    // smem pitch (halves) for W2^T rows
__global__ void __launch_bounds__(256) k_gemm2_mma(const float* __restrict__ W2,
                                                   const float* __restrict__ gamma,
                                                   const float* __restrict__ beta) {
    __shared__ __align__(16) __half sWT[64 * P2];   // W2^T: [n][k] fp16
    __shared__ __align__(16) float s_sc[DH], s_sh[DH];
    const int tid = threadIdx.x, warp = tid >> 5, lane = tid & 31;
    const int quad = lane >> 2, tq = lane & 3;

    for (int i = tid; i < 64 * 64; i += 256) {
        int n = i & 63, k = i >> 6;
        sWT[n * P2 + k] = __float2half(__ldg(&W2[k * 64 + n]));
    }
    if (tid < DH) {
        float mean = g_sum1[tid] * (1.f / NN);
        float var  = g_sq1[tid] * (1.f / NN) - mean * mean;
        float inv  = rsqrtf(var + BN_EPS);
        float sc   = __ldg(&gamma[tid]) * inv;
        s_sc[tid] = sc;
        s_sh[tid] = __ldg(&beta[tid]) - mean * sc;
    }
    __syncthreads();

    int r0 = blockIdx.x * 128 + warp * 16;
    int ra  = min(r0 + quad,     NN - 1);
    int ra8 = min(r0 + quad + 8, NN - 1);
    const float* pr  = g_agg + (size_t)ra  * DH;
    const float* pr8 = g_agg + (size_t)ra8 * DH;

    float acc[8][4];
    #pragma unroll
    for (int n = 0; n < 8; ++n) { acc[n][0] = acc[n][1] = acc[n][2] = acc[n][3] = 0.f; }

    #pragma unroll
    for (int ks = 0; ks < 4; ++ks) {
        int k0 = ks * 16 + tq * 2;
        float2 sc0 = *(const float2*)&s_sc[k0],     sh0 = *(const float2*)&s_sh[k0];
        float2 sc8 = *(const float2*)&s_sc[k0 + 8], sh8 = *(const float2*)&s_sh[k0 + 8];
        float2 v0 = __ldg((const float2*)&pr[k0]);
        float2 v1 = __ldg((const float2*)&pr8[k0]);
        float2 v2 = __ldg((const float2*)&pr[k0 + 8]);
        float2 v3 = __ldg((const float2*)&pr8[k0 + 8]);
        unsigned a0 = h2u(fmaxf(fmaf(v0.x, sc0.x, sh0.x), 0.f), fmaxf(fmaf(v0.y, sc0.y, sh0.y), 0.f));
        unsigned a1 = h2u(fmaxf(fmaf(v1.x, sc0.x, sh0.x), 0.f), fmaxf(fmaf(v1.y, sc0.y, sh0.y), 0.f));
        unsigned a2 = h2u(fmaxf(fmaf(v2.x, sc8.x, sh8.x), 0.f), fmaxf(fmaf(v2.y, sc8.y, sh8.y), 0.f));
        unsigned a3 = h2u(fmaxf(fmaf(v3.x, sc8.x, sh8.x), 0.f), fmaxf(fmaf(v3.y, sc8.y, sh8.y), 0.f));
        #pragma unroll
        for (int n = 0; n < 8; ++n) {
            const __half* bp = &sWT[(n * 8 + quad) * P2 + k0];
            unsigned b0 = *(const unsigned*)bp;
            unsigned b1 = *(const unsigned*)(bp + 8);
            MMA16816(acc[n], a0, a1, a2, a3, b0, b1);
        }
    }

    unsigned* gh = (unsigned*)g_h;
    int r = r0 + quad;
    #pragma unroll
    for (int n = 0; n < 8; ++n) {
        int cw = n * 4 + tq;
        if (r < NN)     gh[(size_t)r * 32 + cw]       = h2u(acc[n][0], acc[n][1]);
        if (r + 8 < NN) gh[(size_t)(r + 8) * 32 + cw] = h2u(acc[n][2], acc[n][3]);
    }
}

// ---------------- CSR gather agg + bias, fused column stats ----------------
__global__ void __launch_bounds__(256) k_agg(const float* __restrict__ bias,
                                             float* __restrict__ gsum,
                                             float* __restrict__ gsq) {
    __shared__ float s_sum[DH], s_sq[DH];
    if (threadIdx.x < DH) { s_sum[threadIdx.x] = 0.f; s_sq[threadIdx.x] = 0.f; }
    __syncthreads();
    int gw = blockIdx.x * 8 + (threadIdx.x >> 5);
    int lane = threadIdx.x & 31;
    int beg = rowbeg(gw);
    int end = (gw == NN - 1) ? TOT : rowbeg(gw + 1);
    const __half2* hp = g_h;
    float2 acc = {0.f, 0.f};
    int j = beg;
    for (; j + 4 <= end; j += 4) {
        int2 c0 = g_cv[j], c1 = g_cv[j + 1], c2 = g_cv[j + 2], c3 = g_cv[j + 3];
        float2 h0 = __half22float2(__ldg(&hp[(size_t)c0.x * 32 + lane]));
        float2 h1 = __half22float2(__ldg(&hp[(size_t)c1.x * 32 + lane]));
        float2 h2 = __half22float2(__ldg(&hp[(size_t)c2.x * 32 + lane]));
        float2 h3 = __half22float2(__ldg(&hp[(size_t)c3.x * 32 + lane]));
        float v0 = __int_as_float(c0.y), v1 = __int_as_float(c1.y);
        float v2 = __int_as_float(c2.y), v3 = __int_as_float(c3.y);
        acc.x += v0 * h0.x; acc.y += v0 * h0.y;
        acc.x += v1 * h1.x; acc.y += v1 * h1.y;
        acc.x += v2 * h2.x; acc.y += v2 * h2.y;
        acc.x += v3 * h3.x; acc.y += v3 * h3.y;
    }
    for (; j < end; ++j) {
        int2 c = g_cv[j];
        float2 hv = __half22float2(__ldg(&hp[(size_t)c.x * 32 + lane]));
        float v = __int_as_float(c.y);
        acc.x += v * hv.x; acc.y += v * hv.y;
    }
    float di = g_dinv[gw];
    acc.x = acc.x * di + __ldg(&bias[2 * lane]);
    acc.y = acc.y * di + __ldg(&bias[2 * lane + 1]);
    *(float2*)&g_agg[(size_t)gw * DH + 2 * lane] = acc;
    atomicAdd(&s_sum[2 * lane],     acc.x);
    atomicAdd(&s_sum[2 * lane + 1], acc.y);
    atomicAdd(&s_sq[2 * lane],      acc.x * acc.x);
    atomicAdd(&s_sq[2 * lane + 1],  acc.y * acc.y);
    __syncthreads();
    if (threadIdx.x < DH) {
        atomicAdd(&gsum[threadIdx.x], s_sum[threadIdx.x]);
        atomicAdd(&gsq[threadIdx.x],  s_sq[threadIdx.x]);
    }
}

// ---------------- final: out = relu(bn2(g_agg)) ----------------
__global__ void __launch_bounds__(256) k_final(const float* __restrict__ gamma,
                                               const float* __restrict__ beta,
                                               float* __restrict__ out) {
    __shared__ float ssc[DH], ssh[DH];
    if (threadIdx.x < DH) {
        int c = threadIdx.x;
        float mean = g_sum2[c] * (1.f / NN);
        float var  = g_sq2[c] * (1.f / NN) - mean * mean;
        float inv  = rsqrtf(var + BN_EPS);
        float sc   = __ldg(&gamma[c]) * inv;
        ssc[c] = sc;
        ssh[c] = __ldg(&beta[c]) - mean * sc;
    }
    __syncthreads();
    int idx = blockIdx.x * blockDim.x + threadIdx.x;
    if (idx >= NN * (DH / 4)) return;
    float4 v = ((const float4*)g_agg)[idx];
    int cb = (idx & (DH / 4 - 1)) * 4;
    v.x = fmaxf(fmaf(v.x, ssc[cb + 0], ssh[cb + 0]), 0.f);
    v.y = fmaxf(fmaf(v.y, ssc[cb + 1], ssh[cb + 1]), 0.f);
    v.z = fmaxf(fmaf(v.z, ssc[cb + 2], ssh[cb + 2]), 0.f);
    v.w = fmaxf(fmaf(v.w, ssc[cb + 3], ssh[cb + 3]), 0.f);
    ((float4*)out)[idx] = v;
}

// ---------------- launch ----------------
extern "C" void kernel_launch(void* const* d_in, const int* in_sizes, int n_in,
                              void* d_out, int out_size) {
    const float* x      = (const float*)d_in[0];
    const void*  ei_sc  = d_in[1];
    const float* wsc    = (const float*)d_in[2];
    const float* wfc    = (const float*)d_in[4];
    const float* alpha  = (const float*)d_in[5];
    const float* W1     = (const float*)d_in[6];
    const float* b1     = (const float*)d_in[7];
    const float* W2     = (const float*)d_in[8];
    const float* b2     = (const float*)d_in[9];
    const float* gamma1 = (const float*)d_in[10];
    const float* beta1  = (const float*)d_in[11];
    const float* gamma2 = (const float*)d_in[12];
    const float* beta2  = (const float*)d_in[13];
    float*       out    = (float*)d_out;

    const int TB = 256;
    float* d_sum1; cudaGetSymbolAddress((void**)&d_sum1, g_sum1);
    float* d_sq1;  cudaGetSymbolAddress((void**)&d_sq1,  g_sq1);
    float* d_sum2; cudaGetSymbolAddress((void**)&d_sum2, g_sum2);
    float* d_sq2;  cudaGetSymbolAddress((void**)&d_sq2,  g_sq2);

    static cudaStream_t s2 = nullptr;
    static cudaEvent_t ev_fork = nullptr, ev_join = nullptr;
    if (!s2) {
        cudaStreamCreateWithFlags(&s2, cudaStreamNonBlocking);
        cudaEventCreateWithFlags(&ev_fork, cudaEventDisableTiming);
        cudaEventCreateWithFlags(&ev_join, cudaEventDisableTiming);
    }

    k_init<<<(NN + TB - 1) / TB, TB>>>((const int*)ei_sc);
    // fork: gemm1 depends only on x/W1; overlaps with edge preprocessing
    cudaEventRecord(ev_fork, 0);
    cudaStreamWaitEvent(s2, ev_fork, 0);
    k_gemm1_mma<<<GBLK, TB, 0, s2>>>(x, W1);
    cudaEventRecord(ev_join, s2);

    k_edge_prep<<<(NE + TB - 1) / TB, TB>>>(ei_sc, wsc, wfc, alpha);
    k_scan<<<NB_SCAN, SCAN_B>>>();
    k_fill<<<(NE + NN + TB - 1) / TB, TB>>>();

    cudaStreamWaitEvent(0, ev_join, 0);
    k_agg<<<NN / 8, TB>>>(b1, d_sum1, d_sq1);
    k_gemm2_mma<<<GBLK, TB>>>(W2, gamma1, beta1);
    k_agg<<<NN / 8, TB>>>(b2, d_sum2, d_sq2);
    k_final<<<(NN * (DH / 4) + TB - 1) / TB, TB>>>(gamma2, beta2, out);
}